// round 1
// baseline (speedup 1.0000x reference)
#include <cuda_runtime.h>
#include <math_constants.h>

// ---------------- problem constants ----------------
#define N_NODES 20000
#define N_EDGES 320000
#define F_IN    256
#define HIDC    64
#define HEADS   8
#define NCLS    64
#define HC1     (HEADS*HIDC)      // 512
#define NEG_SLOPE 0.2f
#define SM_EPS  1e-16f

// ---------------- scratch (static device globals; no allocs) ----------------
__device__ float g_xlr1[(size_t)N_NODES * 1024];   // [N][xl1(512) | xr1(512)]
__device__ float g_h[(size_t)N_NODES * HC1];       // layer-1 output after ELU
__device__ float g_xlr2[(size_t)N_NODES * 128];    // [N][xl2(64) | xr2(64)]
__device__ float g_alpha1[(size_t)N_EDGES * HEADS];
__device__ float g_alpha2[N_EDGES];
__device__ int   g_deg[N_NODES];
__device__ int   g_off[N_NODES + 1];
__device__ int   g_cur[N_NODES];
__device__ int   g_perm[N_EDGES];

// ---------------- CSR build ----------------
__global__ void hist_kernel(const int* __restrict__ dst) {
    int e = blockIdx.x * blockDim.x + threadIdx.x;
    if (e < N_EDGES) atomicAdd(&g_deg[dst[e]], 1);
}

__global__ void scan_kernel() {
    __shared__ int sums[1024];
    const int CH = (N_NODES + 1023) / 1024;  // 20
    int t = threadIdx.x;
    int base = t * CH;
    int s = 0;
    for (int i = 0; i < CH; i++) {
        int idx = base + i;
        if (idx < N_NODES) s += g_deg[idx];
    }
    sums[t] = s;
    __syncthreads();
    for (int d = 1; d < 1024; d <<= 1) {
        int v = (t >= d) ? sums[t - d] : 0;
        __syncthreads();
        sums[t] += v;
        __syncthreads();
    }
    int pre = (t == 0) ? 0 : sums[t - 1];
    for (int i = 0; i < CH; i++) {
        int idx = base + i;
        if (idx < N_NODES) {
            g_off[idx] = pre;
            g_cur[idx] = pre;
            pre += g_deg[idx];
        }
    }
    if (t == 0) g_off[N_NODES] = sums[1023];
}

__global__ void scatter_kernel(const int* __restrict__ dst) {
    int e = blockIdx.x * blockDim.x + threadIdx.x;
    if (e < N_EDGES) {
        int p = atomicAdd(&g_cur[dst[e]], 1);
        g_perm[p] = e;
    }
}

// ---------------- fp32 tiled GEMM:  C[m, cofs+n] = sum_k A[m,k]*B[k,n] ----------------
// A row-major [M,K], B row-major [K,Nn], C row-major with leading dim ldc.
template <int BM, int BN, int BK, int TM, int TN>
__global__ void __launch_bounds__(256) sgemm_kernel(
    int M, int Nn, int K,
    const float* __restrict__ A, const float* __restrict__ B,
    float* __restrict__ C, int ldc, int cofs)
{
    __shared__ float As[BK][BM];
    __shared__ float Bs[BK][BN];

    const int tid  = threadIdx.x;
    const int tcol = tid % (BN / TN);   // 16
    const int trow = tid / (BN / TN);   // 16
    const int by = blockIdx.y, bx = blockIdx.x;

    float acc[TM][TN];
#pragma unroll
    for (int i = 0; i < TM; i++)
#pragma unroll
        for (int j = 0; j < TN; j++) acc[i][j] = 0.f;

    for (int k0 = 0; k0 < K; k0 += BK) {
        // load A tile (BM x BK) as float4 along K
#pragma unroll
        for (int i = 0; i < (BM * BK) / (256 * 4); i++) {
            int f  = tid + 256 * i;
            int r  = f / (BK / 4);
            int kk = (f % (BK / 4)) * 4;
            int grow = by * BM + r;
            float4 v = make_float4(0.f, 0.f, 0.f, 0.f);
            if (grow < M) v = *(const float4*)(A + (size_t)grow * K + k0 + kk);
            As[kk + 0][r] = v.x;
            As[kk + 1][r] = v.y;
            As[kk + 2][r] = v.z;
            As[kk + 3][r] = v.w;
        }
        // load B tile (BK x BN) as float4 along N
#pragma unroll
        for (int i = 0; i < (BK * BN) / (256 * 4); i++) {
            int f  = tid + 256 * i;
            int r  = f / (BN / 4);
            int nn = (f % (BN / 4)) * 4;
            float4 v = *(const float4*)(B + (size_t)(k0 + r) * Nn + bx * BN + nn);
            *(float4*)&Bs[r][nn] = v;
        }
        __syncthreads();

#pragma unroll
        for (int k = 0; k < BK; k++) {
            float ra[TM], rb[TN];
#pragma unroll
            for (int i = 0; i < TM; i += 4)
                *(float4*)&ra[i] = *(const float4*)&As[k][trow * TM + i];
#pragma unroll
            for (int j = 0; j < TN; j += 4)
                *(float4*)&rb[j] = *(const float4*)&Bs[k][tcol * TN + j];
#pragma unroll
            for (int i = 0; i < TM; i++)
#pragma unroll
                for (int j = 0; j < TN; j++) acc[i][j] += ra[i] * rb[j];
        }
        __syncthreads();
    }

#pragma unroll
    for (int i = 0; i < TM; i++) {
        int grow = by * BM + trow * TM + i;
        if (grow < M) {
            float4 v = make_float4(acc[i][0], acc[i][1], acc[i][2], acc[i][3]);
            *(float4*)(C + (size_t)grow * ldc + cofs + bx * BN + tcol * TN) = v;
        }
    }
}

// ---------------- per-edge GATv2 scores, layer 1 (8 heads) ----------------
__global__ void alpha1_kernel(const int* __restrict__ src, const int* __restrict__ dst,
                              const float* __restrict__ att1)
{
    int e = blockIdx.x * 8 + (threadIdx.x >> 5);
    if (e >= N_EDGES) return;
    int lane = threadIdx.x & 31;
    const float* pl = g_xlr1 + (size_t)src[e] * 1024;         // xl1[src]
    const float* pr = g_xlr1 + (size_t)dst[e] * 1024 + 512;   // xr1[dst]
#pragma unroll
    for (int h = 0; h < HEADS; h++) {
        int c0 = h * 64 + lane;
        float u = pl[c0] + pr[c0];
        u = u > 0.f ? u : NEG_SLOPE * u;
        float v = pl[c0 + 32] + pr[c0 + 32];
        v = v > 0.f ? v : NEG_SLOPE * v;
        float s = att1[c0] * u + att1[c0 + 32] * v;
#pragma unroll
        for (int o = 16; o; o >>= 1) s += __shfl_xor_sync(0xffffffffu, s, o);
        if (lane == 0) g_alpha1[(size_t)e * HEADS + h] = s;
    }
}

// ---------------- per-node softmax + aggregate + bias + ELU, layer 1 ----------------
// one block per node; warp h handles head h (64 channels, 2 per lane)
__global__ void node1_kernel(const int* __restrict__ src, const float* __restrict__ b1)
{
    int n = blockIdx.x;
    int h = threadIdx.x >> 5, lane = threadIdx.x & 31;
    int beg = g_off[n], end = g_off[n + 1];

    float m = -CUDART_INF_F;
    for (int i = beg; i < end; i++)
        m = fmaxf(m, g_alpha1[(size_t)g_perm[i] * HEADS + h]);
    float ssum = 0.f;
    for (int i = beg; i < end; i++)
        ssum += __expf(g_alpha1[(size_t)g_perm[i] * HEADS + h] - m);
    float inv = 1.f / (ssum + SM_EPS);

    float a0 = 0.f, a1 = 0.f;
    for (int i = beg; i < end; i++) {
        int e = g_perm[i];
        float w = __expf(g_alpha1[(size_t)e * HEADS + h] - m) * inv;
        const float* p = g_xlr1 + (size_t)src[e] * 1024 + h * 64;
        a0 += w * p[lane];
        a1 += w * p[lane + 32];
    }
    int c0 = h * 64 + lane;
    float v0 = a0 + b1[c0];
    float v1 = a1 + b1[c0 + 32];
    g_h[(size_t)n * HC1 + c0]      = v0 > 0.f ? v0 : __expf(v0) - 1.f;
    g_h[(size_t)n * HC1 + c0 + 32] = v1 > 0.f ? v1 : __expf(v1) - 1.f;
}

// ---------------- per-edge score, layer 2 (1 head) ----------------
__global__ void alpha2_kernel(const int* __restrict__ src, const int* __restrict__ dst,
                              const float* __restrict__ att2)
{
    int e = blockIdx.x * 8 + (threadIdx.x >> 5);
    if (e >= N_EDGES) return;
    int lane = threadIdx.x & 31;
    const float* pl = g_xlr2 + (size_t)src[e] * 128;
    const float* pr = g_xlr2 + (size_t)dst[e] * 128 + 64;
    float u = pl[lane] + pr[lane];
    u = u > 0.f ? u : NEG_SLOPE * u;
    float v = pl[lane + 32] + pr[lane + 32];
    v = v > 0.f ? v : NEG_SLOPE * v;
    float s = att2[lane] * u + att2[lane + 32] * v;
#pragma unroll
    for (int o = 16; o; o >>= 1) s += __shfl_xor_sync(0xffffffffu, s, o);
    if (lane == 0) g_alpha2[e] = s;
}

// ---------------- per-node softmax + aggregate + bias, layer 2 -> output ----------------
__global__ void node2_kernel(const int* __restrict__ src, const float* __restrict__ b2,
                             float* __restrict__ out)
{
    int n = blockIdx.x;
    int t = threadIdx.x;  // 64 threads = 64 channels
    int beg = g_off[n], end = g_off[n + 1];

    float m = -CUDART_INF_F;
    for (int i = beg; i < end; i++) m = fmaxf(m, g_alpha2[g_perm[i]]);
    float ssum = 0.f;
    for (int i = beg; i < end; i++) ssum += __expf(g_alpha2[g_perm[i]] - m);
    float inv = 1.f / (ssum + SM_EPS);

    float acc = 0.f;
    for (int i = beg; i < end; i++) {
        int e = g_perm[i];
        float w = __expf(g_alpha2[e] - m) * inv;
        acc += w * g_xlr2[(size_t)src[e] * 128 + t];
    }
    out[(size_t)n * NCLS + t] = acc + b2[t];
}

// ---------------- launch ----------------
extern "C" void kernel_launch(void* const* d_in, const int* in_sizes, int n_in,
                              void* d_out, int out_size)
{
    (void)in_sizes; (void)n_in; (void)out_size;
    const float* x    = (const float*)d_in[0];
    const int*   ei   = (const int*)d_in[1];
    const int*   src  = ei;
    const int*   dst  = ei + N_EDGES;
    const float* Wl1  = (const float*)d_in[2];
    const float* Wr1  = (const float*)d_in[3];
    const float* att1 = (const float*)d_in[4];
    const float* b1   = (const float*)d_in[5];
    const float* Wl2  = (const float*)d_in[6];
    const float* Wr2  = (const float*)d_in[7];
    const float* att2 = (const float*)d_in[8];
    const float* b2   = (const float*)d_in[9];
    float* out = (float*)d_out;

    void *p_deg, *p_xlr1, *p_h, *p_xlr2;
    cudaGetSymbolAddress(&p_deg, g_deg);
    cudaGetSymbolAddress(&p_xlr1, g_xlr1);
    cudaGetSymbolAddress(&p_h, g_h);
    cudaGetSymbolAddress(&p_xlr2, g_xlr2);

    // CSR build (per-launch, deterministic up to fp-neutral within-segment order)
    cudaMemsetAsync(p_deg, 0, N_NODES * sizeof(int), 0);
    hist_kernel<<<(N_EDGES + 255) / 256, 256>>>(dst);
    scan_kernel<<<1, 1024>>>();
    scatter_kernel<<<(N_EDGES + 255) / 256, 256>>>(dst);

    // layer-1 projections: xl1 | xr1 -> g_xlr1 [N,1024]
    {
        dim3 grid(HC1 / 64, (N_NODES + 127) / 128);
        sgemm_kernel<128, 64, 16, 8, 4><<<grid, 256>>>(
            N_NODES, HC1, F_IN, x, Wl1, (float*)p_xlr1, 1024, 0);
        sgemm_kernel<128, 64, 16, 8, 4><<<grid, 256>>>(
            N_NODES, HC1, F_IN, x, Wr1, (float*)p_xlr1, 1024, 512);
    }
    alpha1_kernel<<<(N_EDGES + 7) / 8, 256>>>(src, dst, att1);
    node1_kernel<<<N_NODES, 256>>>(src, b1);

    // layer-2 projections: xl2 | xr2 -> g_xlr2 [N,128]
    {
        dim3 grid(1, (N_NODES + 127) / 128);
        sgemm_kernel<128, 64, 16, 8, 4><<<grid, 256>>>(
            N_NODES, NCLS, HC1, (const float*)p_h, Wl2, (float*)p_xlr2, 128, 0);
        sgemm_kernel<128, 64, 16, 8, 4><<<grid, 256>>>(
            N_NODES, NCLS, HC1, (const float*)p_h, Wr2, (float*)p_xlr2, 128, 64);
    }
    alpha2_kernel<<<(N_EDGES + 7) / 8, 256>>>(src, dst, att2);
    node2_kernel<<<N_NODES, 64>>>(src, b2, out);
}